// round 1
// baseline (speedup 1.0000x reference)
#include <cuda_runtime.h>

#define THREADS 224
#define IMGS 8

// Packed / quantized weights produced by prep_kernel each launch.
__device__ float g_w1q[36];     // s1 * sign, OIHW flat (4x1x3x3)
__device__ int   g_w2p[36];     // word[oc*9+tap], bytes = int8 sign per ic
__device__ int   g_wfp[490];    // word[o*49+g], bytes = int8 sign, j = 4g+b (j = c*49 + y*7 + x)
__device__ float g_sc[2];       // {s2, 2*sf}

__global__ void prep_kernel(const float* __restrict__ w1,
                            const float* __restrict__ w2,
                            const float* __restrict__ wf) {
    __shared__ float red[256];
    __shared__ float sS[3];
    int tid = threadIdx.x;

    // --- max|w1| ---
    float m = 0.f;
    for (int i = tid; i < 36; i += 256) m = fmaxf(m, fabsf(w1[i]));
    red[tid] = m; __syncthreads();
    for (int s = 128; s > 0; s >>= 1) { if (tid < s) red[tid] = fmaxf(red[tid], red[tid + s]); __syncthreads(); }
    if (tid == 0) sS[0] = red[0];
    __syncthreads();

    // --- max|w2| ---
    m = 0.f;
    for (int i = tid; i < 144; i += 256) m = fmaxf(m, fabsf(w2[i]));
    red[tid] = m; __syncthreads();
    for (int s = 128; s > 0; s >>= 1) { if (tid < s) red[tid] = fmaxf(red[tid], red[tid + s]); __syncthreads(); }
    if (tid == 0) sS[1] = red[0];
    __syncthreads();

    // --- max|wf| ---
    m = 0.f;
    for (int i = tid; i < 1960; i += 256) m = fmaxf(m, fabsf(wf[i]));
    red[tid] = m; __syncthreads();
    for (int s = 128; s > 0; s >>= 1) { if (tid < s) red[tid] = fmaxf(red[tid], red[tid + s]); __syncthreads(); }
    if (tid == 0) sS[2] = red[0];
    __syncthreads();

    float s1 = sS[0], s2 = sS[1], sf = sS[2];

    // quantized fp32 conv1 weights (value = s1 * clip(rint(w/s1),-1,1))
    if (tid < 36) {
        float q = rintf(w1[tid] / s1);
        q = fminf(fmaxf(q, -1.f), 1.f);
        g_w1q[tid] = q * s1;
    }
    // conv2 sign pack: word per (oc, tap), byte ic
    if (tid >= 64 && tid < 100) {
        int t = tid - 64;
        int oc = t / 9, tap = t % 9;
        int word = 0;
        for (int ic = 0; ic < 4; ic++) {
            float w = w2[(oc * 4 + ic) * 9 + tap];
            int si = (int)rintf(w / s2);
            si = min(1, max(-1, si));
            word |= (si & 0xFF) << (8 * ic);
        }
        g_w2p[t] = word;
    }
    // FC sign pack: j = c*49 + p flatten order, 4 bytes per word
    for (int g = tid; g < 490; g += 256) {
        int o = g / 49, gg = g % 49;
        int word = 0;
        for (int b4 = 0; b4 < 4; b4++) {
            int j = gg * 4 + b4;
            float w = wf[o * 196 + j];
            int si = (int)rintf(w / sf);
            si = min(1, max(-1, si));
            word |= (si & 0xFF) << (8 * b4);
        }
        g_wfp[g] = word;
    }
    if (tid == 0) { g_sc[0] = s2; g_sc[1] = 2.f * sf; }
}

__global__ __launch_bounds__(THREADS, 2)
void net_main(const float* __restrict__ x, float* __restrict__ out) {
    __shared__ float inp[IMGS][30][33];   // zero halo, pad 33 to break bank conflicts
    __shared__ int   lvl1[16][17];        // conv1+quant+pool levels, packed 4ch/byte, zero halo
    __shared__ int   c2acc[14][14][4];    // conv2 integer accumulators
    __shared__ float sw1[36];
    __shared__ int   sw2[36];
    __shared__ int   swf[490];
    __shared__ int   flatw[49];           // 196 int8 levels in FC flatten order
    __shared__ float ssc[2];

    int tid = threadIdx.x;

    // zero halos + stage weights to smem
    float* inpf = &inp[0][0][0];
    for (int i = tid; i < IMGS * 30 * 33; i += THREADS) inpf[i] = 0.f;
    for (int i = tid; i < 16 * 17; i += THREADS) ((int*)lvl1)[i] = 0;
    if (tid < 36) { sw1[tid] = g_w1q[tid]; sw2[tid] = g_w2p[tid]; }
    for (int i = tid; i < 490; i += THREADS) swf[i] = g_wfp[i];
    if (tid < 2) ssc[tid] = g_sc[tid];
    __syncthreads();

    // conv1 weights -> registers (critical: keeps LDS below FMA rate)
    float rw1[36];
#pragma unroll
    for (int i = 0; i < 36; i++) rw1[i] = sw1[i];

    // vectorized load of 8 images (1568 float4 = 224*7, rows of 28 = 7 float4 exactly)
    const float4* xb = (const float4*)(x + (size_t)blockIdx.x * (IMGS * 784));
#pragma unroll
    for (int k = 0; k < 7; k++) {
        int q = tid + k * THREADS;
        float4 v = xb[q];
        int img = q / 196;
        int r4 = q - img * 196;
        int y = r4 / 7;
        int x4 = (r4 - y * 7) * 4;
        inp[img][y + 1][x4 + 1] = v.x;
        inp[img][y + 1][x4 + 2] = v.y;
        inp[img][y + 1][x4 + 3] = v.z;
        inp[img][y + 1][x4 + 4] = v.w;
    }
    __syncthreads();

    bool act = tid < 196;
    int py = tid / 14, px = tid - (tid / 14) * 14;
    float s2 = ssc[0], osc = ssc[1];

    for (int img = 0; img < IMGS; img++) {
        // ---- Phase B: conv1 (fp32) + quant + 2x2 maxpool (quant is monotone -> pool first in fp) ----
        if (act) {
            float p[4][4];
#pragma unroll
            for (int r = 0; r < 4; r++)
#pragma unroll
                for (int c = 0; c < 4; c++)
                    p[r][c] = inp[img][2 * py + r][2 * px + c];
            int pack = 0;
#pragma unroll
            for (int ch = 0; ch < 4; ch++) {
                float a00 = 0.f, a01 = 0.f, a10 = 0.f, a11 = 0.f;
#pragma unroll
                for (int ky = 0; ky < 3; ky++)
#pragma unroll
                    for (int kx = 0; kx < 3; kx++) {
                        float wv = rw1[ch * 9 + ky * 3 + kx];
                        a00 = fmaf(wv, p[ky][kx],         a00);
                        a01 = fmaf(wv, p[ky][kx + 1],     a01);
                        a10 = fmaf(wv, p[ky + 1][kx],     a10);
                        a11 = fmaf(wv, p[ky + 1][kx + 1], a11);
                    }
                float mx = fmaxf(fmaxf(a00, a01), fmaxf(a10, a11));
                int lv = __float2int_rn(fminf(fmaxf(mx, 0.f), 6.f) * 0.5f);  // level 0..3
                pack |= lv << (8 * ch);
            }
            lvl1[py + 1][px + 1] = pack;
        }
        __syncthreads();

        // ---- Phase C: conv2 as exact int8 dp4a over packed channels ----
        if (act) {
            int a[9];
#pragma unroll
            for (int r = 0; r < 3; r++)
#pragma unroll
                for (int c = 0; c < 3; c++)
                    a[r * 3 + c] = lvl1[py + r][px + c];
#pragma unroll
            for (int oc = 0; oc < 4; oc++) {
                int acc = 0;
#pragma unroll
                for (int k = 0; k < 9; k++) acc = __dp4a(a[k], sw2[oc * 9 + k], acc);
                c2acc[py][px][oc] = acc;
            }
        }
        __syncthreads();

        // ---- Phase pool2 + quant (integer max, single quantize): level = clamp(rint(s2*acc),0,3) ----
        if (tid < 49) {
            int qy = tid / 7, qx = tid - (tid / 7) * 7;
            unsigned char* fb = (unsigned char*)flatw;
#pragma unroll
            for (int c = 0; c < 4; c++) {
                int m0 = max(c2acc[2 * qy][2 * qx][c],     c2acc[2 * qy][2 * qx + 1][c]);
                int m1 = max(c2acc[2 * qy + 1][2 * qx][c], c2acc[2 * qy + 1][2 * qx + 1][c]);
                int mm = max(m0, m1);
                int lv = __float2int_rn(s2 * (float)mm);
                lv = min(3, max(0, lv));
                fb[c * 49 + tid] = (unsigned char)lv;
            }
        }
        __syncthreads();

        // ---- Phase D: FC via dp4a, out = 2*sf * (int dot) ----
        if (tid < 10) {
            int acc = 0;
#pragma unroll
            for (int g = 0; g < 49; g++) acc = __dp4a(flatw[g], swf[tid * 49 + g], acc);
            out[((size_t)blockIdx.x * IMGS + img) * 10 + tid] = osc * (float)acc;
        }
        __syncthreads();  // protect flatw/lvl1 reuse next image
    }
}

extern "C" void kernel_launch(void* const* d_in, const int* in_sizes, int n_in,
                              void* d_out, int out_size) {
    const float* x  = (const float*)d_in[0];
    const float* w1 = (const float*)d_in[1];
    const float* w2 = (const float*)d_in[2];
    const float* wf = (const float*)d_in[3];
    float* out = (float*)d_out;

    prep_kernel<<<1, 256>>>(w1, w2, wf);

    int B = in_sizes[0] / 784;          // 32768
    net_main<<<B / IMGS, THREADS>>>(x, out);
}

// round 2
// speedup vs baseline: 1.8501x; 1.8501x over previous
#include <cuda_runtime.h>

typedef unsigned long long ull;

// Packed / quantized weights produced by prep_kernel each launch.
__device__ float g_w1q[36];     // s1 * sign, OIHW flat (4x1x3x3)
__device__ int   g_w2p[36];     // word[oc*9+tap], bytes = int8 sign per ic
__device__ int   g_wfp[490];    // word[o*49 + qy*7+qx], bytes = sign per channel c=0..3
__device__ float g_sc[2];       // {s2, 2*sf}

__global__ void prep_kernel(const float* __restrict__ w1,
                            const float* __restrict__ w2,
                            const float* __restrict__ wf) {
    __shared__ float red[256];
    __shared__ float sS[3];
    int tid = threadIdx.x;

    float m = 0.f;
    for (int i = tid; i < 36; i += 256) m = fmaxf(m, fabsf(w1[i]));
    red[tid] = m; __syncthreads();
    for (int s = 128; s > 0; s >>= 1) { if (tid < s) red[tid] = fmaxf(red[tid], red[tid + s]); __syncthreads(); }
    if (tid == 0) sS[0] = red[0];
    __syncthreads();

    m = 0.f;
    for (int i = tid; i < 144; i += 256) m = fmaxf(m, fabsf(w2[i]));
    red[tid] = m; __syncthreads();
    for (int s = 128; s > 0; s >>= 1) { if (tid < s) red[tid] = fmaxf(red[tid], red[tid + s]); __syncthreads(); }
    if (tid == 0) sS[1] = red[0];
    __syncthreads();

    m = 0.f;
    for (int i = tid; i < 1960; i += 256) m = fmaxf(m, fabsf(wf[i]));
    red[tid] = m; __syncthreads();
    for (int s = 128; s > 0; s >>= 1) { if (tid < s) red[tid] = fmaxf(red[tid], red[tid + s]); __syncthreads(); }
    if (tid == 0) sS[2] = red[0];
    __syncthreads();

    float s1 = sS[0], s2 = sS[1], sf = sS[2];

    if (tid < 36) {
        float q = rintf(w1[tid] / s1);
        q = fminf(fmaxf(q, -1.f), 1.f);
        g_w1q[tid] = q * s1;
    }
    if (tid >= 64 && tid < 100) {
        int t = tid - 64;
        int oc = t / 9, tap = t % 9;
        int word = 0;
        for (int ic = 0; ic < 4; ic++) {
            float w = w2[(oc * 4 + ic) * 9 + tap];
            int si = (int)rintf(w / s2);
            si = min(1, max(-1, si));
            word |= (si & 0xFF) << (8 * ic);
        }
        g_w2p[t] = word;
    }
    // FC pack: word[o*49 + p] packs channels c=0..3 of flattened index j = c*49 + p
    for (int g = tid; g < 490; g += 256) {
        int o = g / 49, p = g % 49;
        int word = 0;
        for (int c = 0; c < 4; c++) {
            float w = wf[o * 196 + c * 49 + p];
            int si = (int)rintf(w / sf);
            si = min(1, max(-1, si));
            word |= (si & 0xFF) << (8 * c);
        }
        g_wfp[g] = word;
    }
    if (tid == 0) { g_sc[0] = s2; g_sc[1] = 2.f * sf; }
}

__device__ __forceinline__ ull pk2(float v) {
    ull d; asm("mov.b64 %0, {%1, %1};" : "=l"(d) : "f"(v)); return d;
}
__device__ __forceinline__ ull fma2(ull a, ull b, ull c) {
    ull d; asm("fma.rn.f32x2 %0, %1, %2, %3;" : "=l"(d) : "l"(a), "l"(b), "l"(c)); return d;
}
__device__ __forceinline__ float lo2(ull v) { return __uint_as_float((unsigned)v); }
__device__ __forceinline__ float hi2(ull v) { return __uint_as_float((unsigned)(v >> 32)); }

__global__ __launch_bounds__(256)
void net_warp(const float* __restrict__ x, float* __restrict__ out) {
    __shared__ ull   sw1p[18];
    __shared__ int   sw2s[36];
    __shared__ int   swfs[490];
    __shared__ float sscs[2];

    int tid = threadIdx.x;
    if (tid < 18) {
        int k = tid % 9, base = (tid / 9) * 18;
        ull lo = __float_as_uint(g_w1q[base + k]);
        ull hi = __float_as_uint(g_w1q[base + 9 + k]);
        sw1p[tid] = lo | (hi << 32);
    }
    if (tid < 36) sw2s[tid] = g_w2p[tid];
    for (int i = tid; i < 490; i += 256) swfs[i] = g_wfp[i];
    if (tid < 2) sscs[tid] = g_sc[tid];
    __syncthreads();

    const int lane = tid & 31;
    const int img  = blockIdx.x * 8 + (tid >> 5);

    // conv1 weight pairs -> registers
    ull w01[9], w23[9];
#pragma unroll
    for (int k = 0; k < 9; k++) { w01[k] = sw1p[k]; w23[k] = sw1p[9 + k]; }
    const float s2  = sscs[0];
    const float osc = sscs[1];

    // ---- load one image column per lane (lanes 28..31 zero) ----
    const float* xim = x + (size_t)img * 784;
    float in[28];
#pragma unroll
    for (int r = 0; r < 28; r++) {
        float v = 0.f;
        if (lane < 28) v = __ldg(xim + r * 28 + lane);
        in[r] = v;
    }

    // ---- conv1 (FFMA2, streaming rows) + quant + pool1 ----
    ull a01[3], a23[3];
    ull p01 = 0, p23 = 0;
    int lvlall[14];

#define C1_POOL(yc)                                                            \
    {                                                                          \
        const int s_ = (yc) % 3;                                               \
        if (((yc) & 1) == 0) { p01 = a01[s_]; p23 = a23[s_]; }                 \
        else {                                                                 \
            float v0 = fmaxf(lo2(p01), lo2(a01[s_]));                          \
            float v1 = fmaxf(hi2(p01), hi2(a01[s_]));                          \
            float v2 = fmaxf(lo2(p23), lo2(a23[s_]));                          \
            float v3 = fmaxf(hi2(p23), hi2(a23[s_]));                          \
            v0 = fmaxf(v0, __shfl_down_sync(0xffffffffu, v0, 1));              \
            v1 = fmaxf(v1, __shfl_down_sync(0xffffffffu, v1, 1));              \
            v2 = fmaxf(v2, __shfl_down_sync(0xffffffffu, v2, 1));              \
            v3 = fmaxf(v3, __shfl_down_sync(0xffffffffu, v3, 1));              \
            int l0 = __float2int_rn(fminf(fmaxf(v0, 0.f), 6.f) * 0.5f);        \
            int l1 = __float2int_rn(fminf(fmaxf(v1, 0.f), 6.f) * 0.5f);        \
            int l2 = __float2int_rn(fminf(fmaxf(v2, 0.f), 6.f) * 0.5f);        \
            int l3 = __float2int_rn(fminf(fmaxf(v3, 0.f), 6.f) * 0.5f);        \
            lvlall[(yc) >> 1] = l0 | (l1 << 8) | (l2 << 16) | (l3 << 24);      \
        }                                                                      \
    }

#pragma unroll
    for (int r = 0; r < 28; r++) {
        float mv = in[r];
        float lf = __shfl_up_sync(0xffffffffu, mv, 1);
        if (lane == 0) lf = 0.f;
        float rt = __shfl_down_sync(0xffffffffu, mv, 1);   // lane27 reads lane28 = 0
        ull pl = pk2(lf), pm = pk2(mv), pr = pk2(rt);
#pragma unroll
        for (int ky = 0; ky < 3; ky++) {
            const int y = r + 1 - ky;
            if (y < 0 || y > 27) continue;
            const int s = y % 3;
            const bool fresh = (ky == 0) || (y == 0 && r == 0);
            ull c01 = fresh ? 0ull : a01[s];
            ull c23 = fresh ? 0ull : a23[s];
            c01 = fma2(w01[3 * ky + 0], pl, c01);
            c01 = fma2(w01[3 * ky + 1], pm, c01);
            c01 = fma2(w01[3 * ky + 2], pr, c01);
            c23 = fma2(w23[3 * ky + 0], pl, c23);
            c23 = fma2(w23[3 * ky + 1], pm, c23);
            c23 = fma2(w23[3 * ky + 2], pr, c23);
            a01[s] = c01; a23[s] = c23;
        }
        if (r >= 1) C1_POOL(r - 1);
        if (r == 27) C1_POOL(27);
    }

    // ---- redistribute pooled columns: even lanes -> lanes 0..13 ----
    int myl[14];
#pragma unroll
    for (int t = 0; t < 14; t++)
        myl[t] = __shfl_sync(0xffffffffu, lvlall[t], (lane & 15) * 2);
    if (lane >= 14) {
#pragma unroll
        for (int t = 0; t < 14; t++) myl[t] = 0;
    }

    // ---- conv2 (dp4a, streaming rows) + quant + pool2 ----
    int w2r[36];
#pragma unroll
    for (int k = 0; k < 36; k++) w2r[k] = sw2s[k];

    int b0[3], b1[3], b2[3], b3[3];
    int q0 = 0, q1 = 0, q2 = 0, q3 = 0;
    int flat7[7];

#define C2_POOL(yc)                                                            \
    {                                                                          \
        const int s_ = (yc) % 3;                                               \
        if (((yc) & 1) == 0) { q0 = b0[s_]; q1 = b1[s_]; q2 = b2[s_]; q3 = b3[s_]; } \
        else {                                                                 \
            int m0 = max(q0, b0[s_]);                                          \
            int m1 = max(q1, b1[s_]);                                          \
            int m2 = max(q2, b2[s_]);                                          \
            int m3 = max(q3, b3[s_]);                                          \
            m0 = max(m0, __shfl_down_sync(0xffffffffu, m0, 1));                \
            m1 = max(m1, __shfl_down_sync(0xffffffffu, m1, 1));                \
            m2 = max(m2, __shfl_down_sync(0xffffffffu, m2, 1));                \
            m3 = max(m3, __shfl_down_sync(0xffffffffu, m3, 1));                \
            int l0 = min(3, max(0, __float2int_rn(s2 * (float)m0)));           \
            int l1 = min(3, max(0, __float2int_rn(s2 * (float)m1)));           \
            int l2 = min(3, max(0, __float2int_rn(s2 * (float)m2)));           \
            int l3 = min(3, max(0, __float2int_rn(s2 * (float)m3)));           \
            flat7[(yc) >> 1] = l0 | (l1 << 8) | (l2 << 16) | (l3 << 24);       \
        }                                                                      \
    }

#pragma unroll
    for (int rr = 0; rr < 14; rr++) {
        int lv = myl[rr];
        int lL = __shfl_up_sync(0xffffffffu, lv, 1);
        if (lane == 0) lL = 0;
        int lR = __shfl_down_sync(0xffffffffu, lv, 1);  // lane13 reads lane14 = 0
#pragma unroll
        for (int ky = 0; ky < 3; ky++) {
            const int y = rr + 1 - ky;
            if (y < 0 || y > 13) continue;
            const int s = y % 3;
            const bool fresh = (ky == 0) || (y == 0 && rr == 0);
            int c0 = fresh ? 0 : b0[s];
            int c1 = fresh ? 0 : b1[s];
            int c2 = fresh ? 0 : b2[s];
            int c3 = fresh ? 0 : b3[s];
            c0 = __dp4a(lL, w2r[0 * 9 + ky * 3 + 0], c0);
            c0 = __dp4a(lv, w2r[0 * 9 + ky * 3 + 1], c0);
            c0 = __dp4a(lR, w2r[0 * 9 + ky * 3 + 2], c0);
            c1 = __dp4a(lL, w2r[1 * 9 + ky * 3 + 0], c1);
            c1 = __dp4a(lv, w2r[1 * 9 + ky * 3 + 1], c1);
            c1 = __dp4a(lR, w2r[1 * 9 + ky * 3 + 2], c1);
            c2 = __dp4a(lL, w2r[2 * 9 + ky * 3 + 0], c2);
            c2 = __dp4a(lv, w2r[2 * 9 + ky * 3 + 1], c2);
            c2 = __dp4a(lR, w2r[2 * 9 + ky * 3 + 2], c2);
            c3 = __dp4a(lL, w2r[3 * 9 + ky * 3 + 0], c3);
            c3 = __dp4a(lv, w2r[3 * 9 + ky * 3 + 1], c3);
            c3 = __dp4a(lR, w2r[3 * 9 + ky * 3 + 2], c3);
            b0[s] = c0; b1[s] = c1; b2[s] = c2; b3[s] = c3;
        }
        if (rr >= 1) C2_POOL(rr - 1);
        if (rr == 13) C2_POOL(13);
    }

    // ---- FC: broadcast the 49 packed level words; lanes 0..9 own outputs ----
    const int widx = (lane < 10 ? lane : 0) * 49;
    int facc = 0;
#pragma unroll
    for (int qy = 0; qy < 7; qy++) {
#pragma unroll
        for (int qx = 0; qx < 7; qx++) {
            int word = __shfl_sync(0xffffffffu, flat7[qy], qx * 2);
            facc = __dp4a(word, swfs[widx + qy * 7 + qx], facc);
        }
    }
    if (lane < 10)
        out[(size_t)img * 10 + lane] = osc * (float)facc;
}

extern "C" void kernel_launch(void* const* d_in, const int* in_sizes, int n_in,
                              void* d_out, int out_size) {
    const float* x  = (const float*)d_in[0];
    const float* w1 = (const float*)d_in[1];
    const float* w2 = (const float*)d_in[2];
    const float* wf = (const float*)d_in[3];
    float* out = (float*)d_out;

    prep_kernel<<<1, 256>>>(w1, w2, wf);

    int B = in_sizes[0] / 784;          // 32768 images, 8 warps/block = 1 image/warp
    net_warp<<<B / 8, 256>>>(x, out);
}

// round 3
// speedup vs baseline: 2.0912x; 1.1303x over previous
#include <cuda_runtime.h>

typedef unsigned long long ull;

// Packed / quantized weights produced by prep_kernel each launch.
__device__ float g_w1q[36];     // 0.5 * s1 * sign (pre-halved, exact), OIHW flat (4x1x3x3)
__device__ int   g_w2p[36];     // word[oc*9+tap], bytes = int8 sign per ic
__device__ int   g_wfp[490];    // word[o*49 + qy*7+qx], bytes = sign per channel c=0..3
__device__ float g_sc[2];       // {s2, 2*sf}

__global__ void prep_kernel(const float* __restrict__ w1,
                            const float* __restrict__ w2,
                            const float* __restrict__ wf) {
    __shared__ float wmax[8][3];
    __shared__ float sS[3];
    int tid = threadIdx.x, lane = tid & 31, wid = tid >> 5;

    float m1 = 0.f, m2 = 0.f, mf = 0.f;
    if (tid < 36)  m1 = fabsf(w1[tid]);
    if (tid < 144) m2 = fabsf(w2[tid]);
    for (int i = tid; i < 1960; i += 256) mf = fmaxf(mf, fabsf(wf[i]));
#pragma unroll
    for (int o = 16; o; o >>= 1) {
        m1 = fmaxf(m1, __shfl_xor_sync(0xffffffffu, m1, o));
        m2 = fmaxf(m2, __shfl_xor_sync(0xffffffffu, m2, o));
        mf = fmaxf(mf, __shfl_xor_sync(0xffffffffu, mf, o));
    }
    if (lane == 0) { wmax[wid][0] = m1; wmax[wid][1] = m2; wmax[wid][2] = mf; }
    __syncthreads();
    if (tid == 0) {
        float a = 0.f, b = 0.f, c = 0.f;
        for (int w = 0; w < 8; w++) {
            a = fmaxf(a, wmax[w][0]);
            b = fmaxf(b, wmax[w][1]);
            c = fmaxf(c, wmax[w][2]);
        }
        sS[0] = a; sS[1] = b; sS[2] = c;
    }
    __syncthreads();
    float s1 = sS[0], s2 = sS[1], sf = sS[2];

    if (tid < 36) {
        float q = rintf(w1[tid] / s1);
        q = fminf(fmaxf(q, -1.f), 1.f);
        g_w1q[tid] = 0.5f * (q * s1);          // exact halving
    }
    if (tid >= 64 && tid < 100) {
        int t = tid - 64;
        int oc = t / 9, tap = t % 9;
        int word = 0;
        for (int ic = 0; ic < 4; ic++) {
            float w = w2[(oc * 4 + ic) * 9 + tap];
            int si = (int)rintf(w / s2);
            si = min(1, max(-1, si));
            word |= (si & 0xFF) << (8 * ic);
        }
        g_w2p[t] = word;
    }
    for (int g = tid; g < 490; g += 256) {
        int o = g / 49, p = g % 49;
        int word = 0;
        for (int c = 0; c < 4; c++) {
            float w = wf[o * 196 + c * 49 + p];
            int si = (int)rintf(w / sf);
            si = min(1, max(-1, si));
            word |= (si & 0xFF) << (8 * c);
        }
        g_wfp[g] = word;
    }
    if (tid == 0) { g_sc[0] = s2; g_sc[1] = 2.f * sf; }
}

__device__ __forceinline__ ull pk2(float v) {
    ull d; asm("mov.b64 %0, {%1, %1};" : "=l"(d) : "f"(v)); return d;
}
__device__ __forceinline__ ull fma2(ull a, ull b, ull c) {
    ull d; asm("fma.rn.f32x2 %0, %1, %2, %3;" : "=l"(d) : "l"(a), "l"(b), "l"(c)); return d;
}
__device__ __forceinline__ float lo2(ull v) { return __uint_as_float((unsigned)v); }
__device__ __forceinline__ float hi2(ull v) { return __uint_as_float((unsigned)(v >> 32)); }

// level = clamp(rint(v), 0, +inf) with caller pre-clamping top at 3; sat.u32 maps negatives to 0
__device__ __forceinline__ int qlev(float v) {
    unsigned r; asm("cvt.rni.sat.u32.f32 %0, %1;" : "=r"(r) : "f"(v));
    return (int)r;
}
__device__ __forceinline__ int pack4(int a, int b, int c, int d) {
    int ab, cd, r;
    asm("prmt.b32 %0, %1, %2, 0x0040;" : "=r"(ab) : "r"(a), "r"(b));
    asm("prmt.b32 %0, %1, %2, 0x0040;" : "=r"(cd) : "r"(c), "r"(d));
    asm("prmt.b32 %0, %1, %2, 0x5410;" : "=r"(r) : "r"(ab), "r"(cd));
    return r;
}

__global__ __launch_bounds__(256, 3)
void net_warp(const float* __restrict__ x, float* __restrict__ out) {
    __shared__ ull   sw1p[18];
    __shared__ int   sw2s[36];
    __shared__ int   swfs[497];   // 490 weights + 7 zero pad for FC split
    __shared__ float sscs[2];

    int tid = threadIdx.x;
    if (tid < 18) {
        int k = tid % 9, base = (tid / 9) * 18;
        ull lo = __float_as_uint(g_w1q[base + k]);
        ull hi = __float_as_uint(g_w1q[base + 9 + k]);
        sw1p[tid] = lo | (hi << 32);
    }
    if (tid < 36) sw2s[tid] = g_w2p[tid];
    for (int i = tid; i < 490; i += 256) swfs[i] = g_wfp[i];
    if (tid >= 64 && tid < 71) swfs[490 + (tid - 64)] = 0;
    if (tid < 2) sscs[tid] = g_sc[tid];
    __syncthreads();

    const int  lane = tid & 31;
    const int  img  = blockIdx.x * 8 + (tid >> 5);
    const bool isA  = lane < 16;
    const int  lx   = lane & 15;

    ull w01[9], w23[9];
#pragma unroll
    for (int k = 0; k < 9; k++) { w01[k] = sw1p[k]; w23[k] = sw1p[9 + k]; }
    const float s2  = sscs[0];
    const float osc = sscs[1];

    // ---- streaming input: one column per lane (lanes 28..31 = zero), 4-deep prefetch ----
    const bool   colOK = lane < 28;
    const float* xcol  = x + (size_t)img * 784 + lane;
    float buf[4];
#pragma unroll
    for (int i = 0; i < 4; i++) buf[i] = colOK ? __ldg(xcol + i * 28) : 0.f;

    // ---- conv1 (FFMA2, rows streamed) + pool1 + quant + split-redistribution ----
    ull a01[3], a23[3];
    ull p01 = 0, p23 = 0;
    // arr: A lanes (cols, lane 0..13) hold conv1-level rows 0..8;
    //      B lanes (lane 16..29)      hold rows 7..13 in arr[0..6]
    int arr[9];
#pragma unroll
    for (int i = 0; i < 9; i++) arr[i] = 0;

#define C1_POOL(yc)                                                            \
    {                                                                          \
        const int s_ = (yc) % 3;                                               \
        if (((yc) & 1) == 0) { p01 = a01[s_]; p23 = a23[s_]; }                 \
        else {                                                                 \
            float v0 = fmaxf(lo2(p01), lo2(a01[s_]));                          \
            float v1 = fmaxf(hi2(p01), hi2(a01[s_]));                          \
            float v2 = fmaxf(lo2(p23), lo2(a23[s_]));                          \
            float v3 = fmaxf(hi2(p23), hi2(a23[s_]));                          \
            v0 = fmaxf(v0, __shfl_down_sync(0xffffffffu, v0, 1));              \
            v1 = fmaxf(v1, __shfl_down_sync(0xffffffffu, v1, 1));              \
            v2 = fmaxf(v2, __shfl_down_sync(0xffffffffu, v2, 1));              \
            v3 = fmaxf(v3, __shfl_down_sync(0xffffffffu, v3, 1));              \
            int l0 = qlev(fminf(v0, 3.f));                                     \
            int l1 = qlev(fminf(v1, 3.f));                                     \
            int l2 = qlev(fminf(v2, 3.f));                                     \
            int l3 = qlev(fminf(v3, 3.f));                                     \
            int word = pack4(l0, l1, l2, l3);                                  \
            int rv = __shfl_sync(0xffffffffu, word, lx * 2);                   \
            const int t_ = (yc) >> 1;                                          \
            if (t_ <= 8) arr[t_]     = isA  ? rv : arr[t_];                    \
            if (t_ >= 7) arr[t_ - 7] = !isA ? rv : arr[t_ - 7];                \
        }                                                                      \
    }

#pragma unroll
    for (int r = 0; r < 28; r++) {
        float mv = buf[r & 3];
        if (r + 4 < 28) buf[r & 3] = colOK ? __ldg(xcol + (r + 4) * 28) : 0.f;
        float lf = __shfl_up_sync(0xffffffffu, mv, 1);
        if (lane == 0) lf = 0.f;
        float rt = __shfl_down_sync(0xffffffffu, mv, 1);   // lane27 reads lane28 = 0
        ull pl = pk2(lf), pm = pk2(mv), pr = pk2(rt);
#pragma unroll
        for (int ky = 0; ky < 3; ky++) {
            const int y = r + 1 - ky;
            if (y < 0 || y > 27) continue;
            const int s = y % 3;
            const bool fresh = (ky == 0) || (y == 0 && r == 0);
            ull c01 = fresh ? 0ull : a01[s];
            ull c23 = fresh ? 0ull : a23[s];
            c01 = fma2(w01[3 * ky + 0], pl, c01);
            c01 = fma2(w01[3 * ky + 1], pm, c01);
            c01 = fma2(w01[3 * ky + 2], pr, c01);
            c23 = fma2(w23[3 * ky + 0], pl, c23);
            c23 = fma2(w23[3 * ky + 1], pm, c23);
            c23 = fma2(w23[3 * ky + 2], pr, c23);
            a01[s] = c01; a23[s] = c23;
        }
        if (r >= 1) C1_POOL(r - 1);
        if (r == 27) C1_POOL(27);
    }

    // ---- conv2, row-split across half-warps (A: out rows 0..7, B: out rows 8..13) ----
    // Unified stream of 10 steps; local output j consumes stream rows j, j+1, j+2.
    // A stream: [zero, g0..g8]   -> lv = k ? arr[k-1] : 0
    // B stream: [g7..g13, 0, 0, 0] -> lv = (k<=6) ? arr[k] : 0
    int w2r[36];
#pragma unroll
    for (int k = 0; k < 36; k++) w2r[k] = sw2s[k];

    int b0[3], b1[3], b2[3], b3[3];
    int q0 = 0, q1 = 0, q2 = 0, q3r = 0;
    int flat[4];   // A: qy 0..3 at flat[0..3]; B: qy 4..6 at flat[0..2]
    const bool xz0 = (lx == 0), xz13 = (lx == 13);

#pragma unroll
    for (int k = 0; k <= 9; k++) {
        int lv;
        if (k == 0)      lv = isA ? 0 : arr[0];
        else if (k <= 6) lv = isA ? arr[k - 1] : arr[k];
        else             lv = isA ? arr[k - 1] : 0;
        int lL = __shfl_up_sync(0xffffffffu, lv, 1);
        if (xz0)  lL = 0;
        int lR = __shfl_down_sync(0xffffffffu, lv, 1);
        if (xz13) lR = 0;
#pragma unroll
        for (int jj = 0; jj < 3; jj++) {
            const int j = k - jj;                 // local output row
            if (j < 0 || j > 7) continue;
            const int s = j % 3;
            const bool fresh = (jj == 0);
            int c0 = fresh ? 0 : b0[s];
            int c1 = fresh ? 0 : b1[s];
            int c2 = fresh ? 0 : b2[s];
            int c3 = fresh ? 0 : b3[s];
            c0 = __dp4a(lL, w2r[0 * 9 + jj * 3 + 0], c0);
            c0 = __dp4a(lv, w2r[0 * 9 + jj * 3 + 1], c0);
            c0 = __dp4a(lR, w2r[0 * 9 + jj * 3 + 2], c0);
            c1 = __dp4a(lL, w2r[1 * 9 + jj * 3 + 0], c1);
            c1 = __dp4a(lv, w2r[1 * 9 + jj * 3 + 1], c1);
            c1 = __dp4a(lR, w2r[1 * 9 + jj * 3 + 2], c1);
            c2 = __dp4a(lL, w2r[2 * 9 + jj * 3 + 0], c2);
            c2 = __dp4a(lv, w2r[2 * 9 + jj * 3 + 1], c2);
            c2 = __dp4a(lR, w2r[2 * 9 + jj * 3 + 2], c2);
            c3 = __dp4a(lL, w2r[3 * 9 + jj * 3 + 0], c3);
            c3 = __dp4a(lv, w2r[3 * 9 + jj * 3 + 1], c3);
            c3 = __dp4a(lR, w2r[3 * 9 + jj * 3 + 2], c3);
            b0[s] = c0; b1[s] = c1; b2[s] = c2; b3[s] = c3;
        }
        // output row j = k-2 is now complete
        {
            const int j = k - 2;
            if (j >= 0) {
                const int s = j % 3;
                if ((j & 1) == 0) { q0 = b0[s]; q1 = b1[s]; q2 = b2[s]; q3r = b3[s]; }
                else {
                    int m0 = max(q0, b0[s]);
                    int m1 = max(q1, b1[s]);
                    int m2 = max(q2, b2[s]);
                    int m3 = max(q3r, b3[s]);
                    m0 = max(m0, __shfl_down_sync(0xffffffffu, m0, 1));
                    m1 = max(m1, __shfl_down_sync(0xffffffffu, m1, 1));
                    m2 = max(m2, __shfl_down_sync(0xffffffffu, m2, 1));
                    m3 = max(m3, __shfl_down_sync(0xffffffffu, m3, 1));
                    int l0 = qlev(fminf(s2 * (float)m0, 3.f));
                    int l1 = qlev(fminf(s2 * (float)m1, 3.f));
                    int l2 = qlev(fminf(s2 * (float)m2, 3.f));
                    int l3 = qlev(fminf(s2 * (float)m3, 3.f));
                    flat[(j - 1) >> 1] = pack4(l0, l1, l2, l3);
                }
            }
        }
    }

    // ---- FC, split across half-warps: A accumulates qy0..3, B accumulates qy4..6 ----
    // Pooled word for (qy,qx): A group lane 2qx holds qy<=3 in flat[qy];
    //                          B group lane 16+2qx holds qy>=4 in flat[qy-4].
    const int o = min(lx, 9);
    const int laneBase = o * 49 + (isA ? 0 : 28);
    const int grp = lane & 16;
    int facc = 0;
#pragma unroll
    for (int i = 0; i < 28; i++) {
        int word = __shfl_sync(0xffffffffu, flat[i / 7], grp + 2 * (i % 7));
        int widx = laneBase + i;
        if (i >= 21) widx = isA ? widx : 490;   // B has only 21 items; rest hit zero pad
        facc = __dp4a(word, swfs[widx], facc);
    }
    int bpart = __shfl_sync(0xffffffffu, facc, 16 + lx);
    if (lane < 10)
        out[(size_t)img * 10 + lane] = osc * (float)(facc + bpart);
}

extern "C" void kernel_launch(void* const* d_in, const int* in_sizes, int n_in,
                              void* d_out, int out_size) {
    const float* x  = (const float*)d_in[0];
    const float* w1 = (const float*)d_in[1];
    const float* w2 = (const float*)d_in[2];
    const float* wf = (const float*)d_in[3];
    float* out = (float*)d_out;

    prep_kernel<<<1, 256>>>(w1, w2, wf);

    int B = in_sizes[0] / 784;          // 32768 images, 8 warps/block = 1 image/warp
    net_warp<<<B / 8, 256>>>(x, out);
}